// round 4
// baseline (speedup 1.0000x reference)
#include <cuda_runtime.h>
#include <cuda_fp16.h>
#include <cstdint>
#include <math.h>

#define Bdim 128
#define Sdim 128
#define Ddim 256
#define Hdim 8
#define HDim 32
#define Fdim 2048
#define Ldim 4
#define BHdim (Bdim*Hdim)     /* 1024 */
#define NR (Bdim*Sdim)        /* 16384 rows */
#define QKVS 768              /* fused qkv row stride */

// ---------------- scratch (device globals; no allocation allowed) ----------
__device__ float g_x[NR*Ddim];
__device__ float g_qkv[(size_t)NR*QKVS];
__device__ float g_ctx[NR*Ddim];
__device__ float g_tmp[NR*Ddim];
__device__ float g_eb[(size_t)BHdim*Sdim*Sdim];   // [bh][j][i]
__device__ float g_at[(size_t)BHdim*Sdim*Sdim];   // [bh][i][j]
__device__ float g_ff[(size_t)NR*Fdim];
// transposed fp16 weights [N][K]
__device__ __half g_wqkvT[(size_t)Ldim*3*Ddim*Ddim];  // per layer: [768][256]
__device__ __half g_woT[(size_t)Ldim*Ddim*Ddim];      // [256][256]
__device__ __half g_w1T[(size_t)Ldim*Fdim*Ddim];      // [2048][256]
__device__ __half g_w2T[(size_t)Ldim*Ddim*Fdim];      // [256][2048]
__device__ float g_bqkv[Ldim*QKVS];

// ==================== fp16 split-A mma GEMM ================================
// C[M,N] = A[M,K] @ BT[N,K]^T + bias, optional relu.
// A fp32 -> (hi,lo) fp16 split (error-compensated); BT is fp16.
// CTA tile 128x128, 8 warps (4m x 2n), warp tile 32x64, K-chunk 32.
#define CH 32
#define SKH 40                          /* smem halves per row (32 + 8 pad) */
#define TILEH (128 * SKH)               /* 5120 halves = 10240 B */
// buffers: Ahi0 Alo0 B0 Ahi1 Alo1 B1
#define GSM_HALVES (6 * TILEH)
#define GSM_BYTES  (GSM_HALVES * 2)     /* 61440 */

__device__ __forceinline__ void mma_f16(
    float& c0, float& c1, float& c2, float& c3,
    uint32_t a0, uint32_t a1, uint32_t a2, uint32_t a3,
    uint32_t b0, uint32_t b1)
{
    asm volatile(
        "mma.sync.aligned.m16n8k16.row.col.f32.f16.f16.f32 "
        "{%0,%1,%2,%3}, {%4,%5,%6,%7}, {%8,%9}, {%0,%1,%2,%3};"
        : "+f"(c0), "+f"(c1), "+f"(c2), "+f"(c3)
        : "r"(a0), "r"(a1), "r"(a2), "r"(a3), "r"(b0), "r"(b1));
}

template<bool RELU>
__global__ __launch_bounds__(256) void mma_gemm(
    const float* __restrict__ A, const __half* __restrict__ BT,
    const float* __restrict__ bias, float* __restrict__ C,
    int M, int N, int K)
{
    extern __shared__ __half sh[];
    __half* AH[2] = { sh,             sh + 3 * TILEH };
    __half* AL[2] = { sh + TILEH,     sh + 4 * TILEH };
    __half* BH[2] = { sh + 2 * TILEH, sh + 5 * TILEH };
    const int tid = threadIdx.x;
    const int lane = tid & 31, wid = tid >> 5;
    const int wm = (wid >> 1) * 32, wn = (wid & 1) * 64;
    const int m0 = blockIdx.y * 128, n0 = blockIdx.x * 128;
    const float* Abase = A + (size_t)m0 * K;
    const __half* Bbase = BT + (size_t)n0 * K;
    const int nch = K / CH;

    const int srow = tid >> 1;          // 0..127
    const int shalf = tid & 1;          // which 16-wide half of the 32-k chunk

    float4 ra[4];
    uint4 rb[2];
    auto ldg = [&](int c) {
        const float* Ap = Abase + (size_t)srow * K + c * CH + shalf * 16;
#pragma unroll
        for (int i = 0; i < 4; ++i)
            ra[i] = *(const float4*)(Ap + i * 4);
        const __half* Bp = Bbase + (size_t)srow * K + c * CH + shalf * 16;
        rb[0] = *(const uint4*)(Bp);
        rb[1] = *(const uint4*)(Bp + 8);
    };
    auto sts = [&](int buf) {
        const int hb = srow * SKH + shalf * 16;
#pragma unroll
        for (int i = 0; i < 4; ++i) {
            float4 v = ra[i];
            __half hx = __float2half_rn(v.x), hy = __float2half_rn(v.y);
            __half hz = __float2half_rn(v.z), hw = __float2half_rn(v.w);
            __half lx = __float2half_rn(v.x - __half2float(hx));
            __half ly = __float2half_rn(v.y - __half2float(hy));
            __half lz = __float2half_rn(v.z - __half2float(hz));
            __half lw = __float2half_rn(v.w - __half2float(hw));
            union { __half h[4]; uint2 u; } ph, pl;
            ph.h[0] = hx; ph.h[1] = hy; ph.h[2] = hz; ph.h[3] = hw;
            pl.h[0] = lx; pl.h[1] = ly; pl.h[2] = lz; pl.h[3] = lw;
            *(uint2*)&AH[buf][hb + i * 4] = ph.u;
            *(uint2*)&AL[buf][hb + i * 4] = pl.u;
        }
        *(uint4*)&BH[buf][hb]     = rb[0];
        *(uint4*)&BH[buf][hb + 8] = rb[1];
    };

    float acc[2][8][4];
#pragma unroll
    for (int mt = 0; mt < 2; ++mt)
#pragma unroll
        for (int nt = 0; nt < 8; ++nt)
#pragma unroll
            for (int e = 0; e < 4; ++e) acc[mt][nt][e] = 0.f;

    const int qr = lane >> 2;   // group id 0..7
    const int qc = lane & 3;    // thread-in-group 0..3

    ldg(0);
    sts(0);
    __syncthreads();

    for (int c = 0; c < nch; ++c) {
        if (c + 1 < nch) ldg(c + 1);
        const int buf = c & 1;
        const __half* Ah = AH[buf];
        const __half* Al = AL[buf];
        const __half* Bb = BH[buf];
#pragma unroll
        for (int s = 0; s < 2; ++s) {
            const int kb = s * 16;
            uint32_t bf[8][2];
#pragma unroll
            for (int nt = 0; nt < 8; ++nt) {
                const int n = wn + nt * 8 + qr;
                bf[nt][0] = *(const uint32_t*)&Bb[n * SKH + kb + qc * 2];
                bf[nt][1] = *(const uint32_t*)&Bb[n * SKH + kb + 8 + qc * 2];
            }
            uint32_t ah[2][4], al[2][4];
#pragma unroll
            for (int mt = 0; mt < 2; ++mt) {
                const int r = wm + mt * 16 + qr;
                ah[mt][0] = *(const uint32_t*)&Ah[(r    ) * SKH + kb + qc * 2];
                ah[mt][1] = *(const uint32_t*)&Ah[(r + 8) * SKH + kb + qc * 2];
                ah[mt][2] = *(const uint32_t*)&Ah[(r    ) * SKH + kb + 8 + qc * 2];
                ah[mt][3] = *(const uint32_t*)&Ah[(r + 8) * SKH + kb + 8 + qc * 2];
                al[mt][0] = *(const uint32_t*)&Al[(r    ) * SKH + kb + qc * 2];
                al[mt][1] = *(const uint32_t*)&Al[(r + 8) * SKH + kb + qc * 2];
                al[mt][2] = *(const uint32_t*)&Al[(r    ) * SKH + kb + 8 + qc * 2];
                al[mt][3] = *(const uint32_t*)&Al[(r + 8) * SKH + kb + 8 + qc * 2];
            }
#pragma unroll
            for (int nt = 0; nt < 8; ++nt)
#pragma unroll
                for (int mt = 0; mt < 2; ++mt) {
                    mma_f16(acc[mt][nt][0], acc[mt][nt][1],
                            acc[mt][nt][2], acc[mt][nt][3],
                            ah[mt][0], ah[mt][1], ah[mt][2], ah[mt][3],
                            bf[nt][0], bf[nt][1]);
                    mma_f16(acc[mt][nt][0], acc[mt][nt][1],
                            acc[mt][nt][2], acc[mt][nt][3],
                            al[mt][0], al[mt][1], al[mt][2], al[mt][3],
                            bf[nt][0], bf[nt][1]);
                }
        }
        if (c + 1 < nch) {
            __syncthreads();
            sts((c + 1) & 1);
            __syncthreads();
        }
    }

    // epilogue
#pragma unroll
    for (int mt = 0; mt < 2; ++mt) {
        const int r = m0 + wm + mt * 16 + qr;
#pragma unroll
        for (int nt = 0; nt < 8; ++nt) {
            const int col = n0 + wn + nt * 8 + qc * 2;
            float b0 = bias[col], b1 = bias[col + 1];
            float2 v0, v1;
            v0.x = acc[mt][nt][0] + b0; v0.y = acc[mt][nt][1] + b1;
            v1.x = acc[mt][nt][2] + b0; v1.y = acc[mt][nt][3] + b1;
            if (RELU) {
                v0.x = fmaxf(v0.x, 0.f); v0.y = fmaxf(v0.y, 0.f);
                v1.x = fmaxf(v1.x, 0.f); v1.y = fmaxf(v1.y, 0.f);
            }
            *(float2*)(C + (size_t)r * N + col)       = v0;
            *(float2*)(C + (size_t)(r + 8) * N + col) = v1;
        }
    }
}

// ============ weight transposes -> fp16 [N][K] =============================
__global__ __launch_bounds__(256) void tr_qkv(
    const float* __restrict__ Wq, const float* __restrict__ Wk,
    const float* __restrict__ Wv, __half* __restrict__ dst)
{
    __shared__ float t[32][33];
    const int z = blockIdx.z, l = z / 3, w = z % 3;
    const float* src = (w == 0 ? Wq : (w == 1 ? Wk : Wv)) + (size_t)l * Ddim * Ddim;
    __half* d = dst + (size_t)l * 3 * Ddim * Ddim + (size_t)w * Ddim * Ddim;
    const int kx = blockIdx.y * 32, nx = blockIdx.x * 32;
    const int x = threadIdx.x & 31, y = threadIdx.x >> 5;
#pragma unroll
    for (int yy = y; yy < 32; yy += 8)
        t[yy][x] = src[(size_t)(kx + yy) * Ddim + nx + x];
    __syncthreads();
#pragma unroll
    for (int yy = y; yy < 32; yy += 8)
        d[(size_t)(nx + yy) * Ddim + kx + x] = __float2half_rn(t[x][yy]);
}

__global__ __launch_bounds__(256) void tr_h(
    const float* __restrict__ W, __half* __restrict__ WT,
    int K, int N, size_t sstride, size_t dstride)
{
    __shared__ float t[32][33];
    const float* Wl = W + blockIdx.z * sstride;
    __half* WTl = WT + blockIdx.z * dstride;
    const int kx = blockIdx.y * 32, nx = blockIdx.x * 32;
    const int x = threadIdx.x & 31, y = threadIdx.x >> 5;
#pragma unroll
    for (int yy = y; yy < 32; yy += 8)
        t[yy][x] = Wl[(size_t)(kx + yy) * N + nx + x];
    __syncthreads();
#pragma unroll
    for (int yy = y; yy < 32; yy += 8)
        WTl[(size_t)(nx + yy) * K + kx + x] = __float2half_rn(t[x][yy]);
}

// ---- prep: copy facts -> x, and pack qkv bias (single launch) -------------
__global__ void prep_kernel(const float* __restrict__ facts, float* __restrict__ x,
                            const float* __restrict__ bq, const float* __restrict__ bk,
                            const float* __restrict__ bv, float* __restrict__ bqkv)
{
    size_t idx = (size_t)blockIdx.x * 256 + threadIdx.x;
    x[idx] = facts[idx];
    if (idx < Ldim * QKVS) {
        int l = (int)(idx / QKVS), j = (int)(idx % QKVS);
        float v;
        if (j < 256)      v = bq[l * 256 + j];
        else if (j < 512) v = bk[l * 256 + j - 256];
        else              v = bv[l * 256 + j - 512];
        bqkv[idx] = v;
    }
}

// -------- edge-key bias: eb[bh][j][i] = sum_d ek[j,i,d] * q[bh,j,d] --------
__global__ __launch_bounds__(256) void ebias_kernel(
    const float* __restrict__ qkv, const float* __restrict__ ek,
    float* __restrict__ eb)
{
    const int j   = blockIdx.x;
    const int bh0 = blockIdx.y * 128;
    __shared__ float Qs[32][132];
    __shared__ float Es[32][132];
    const int tid = threadIdx.x;
    {
        const int r = tid >> 1;
        const int half = tid & 1;
        const int bh = bh0 + r;
        const int b = bh >> 3, h = bh & 7;
        const float* qp = qkv + (size_t)(b * Sdim + j) * QKVS + h * HDim + half * 16;
        const float* ep = ek + (size_t)(j * Sdim + r) * HDim + half * 16;
#pragma unroll
        for (int c = 0; c < 4; c++) {
            float4 vq = *(const float4*)(qp + c * 4);
            float4 ve = *(const float4*)(ep + c * 4);
            int d = half * 16 + c * 4;
            Qs[d+0][r] = vq.x; Qs[d+1][r] = vq.y; Qs[d+2][r] = vq.z; Qs[d+3][r] = vq.w;
            Es[d+0][r] = ve.x; Es[d+1][r] = ve.y; Es[d+2][r] = ve.z; Es[d+3][r] = ve.w;
        }
    }
    __syncthreads();
    const int ty = tid >> 4, tx = tid & 15;
    float acc[8][8];
#pragma unroll
    for (int i = 0; i < 8; i++)
#pragma unroll
        for (int c = 0; c < 8; c++) acc[i][c] = 0.f;
#pragma unroll
    for (int d = 0; d < 32; d++) {
        float af[8], bf[8];
        *(float4*)&af[0] = *(const float4*)&Qs[d][ty * 8];
        *(float4*)&af[4] = *(const float4*)&Qs[d][ty * 8 + 4];
        *(float4*)&bf[0] = *(const float4*)&Es[d][tx * 8];
        *(float4*)&bf[4] = *(const float4*)&Es[d][tx * 8 + 4];
#pragma unroll
        for (int i = 0; i < 8; i++)
#pragma unroll
            for (int c = 0; c < 8; c++) acc[i][c] += af[i] * bf[c];
    }
#pragma unroll
    for (int i = 0; i < 8; i++) {
        float* op = eb + ((size_t)(bh0 + ty * 8 + i) * Sdim + j) * Sdim + tx * 8;
        *(float4*)(op)     = *(float4*)&acc[i][0];
        *(float4*)(op + 4) = *(float4*)&acc[i][4];
    }
}

// -------- attention per (b,h) ---------------------------------------------
#define ATT_FLOATS (2*32*132 + 128*32 + 128*129)
#define ATT_BYTES  (ATT_FLOATS * 4)
__global__ __launch_bounds__(256) void attn_kernel(
    const float* __restrict__ qkv, const float* __restrict__ eb,
    const unsigned char* __restrict__ mask,
    float* __restrict__ attn_out, float* __restrict__ ctx)
{
    extern __shared__ float sm[];
    float (*Qs)[132] = (float(*)[132])sm;
    float (*Ks)[132] = (float(*)[132])(sm + 32 * 132);
    float (*Vs)[32]  = (float(*)[32]) (sm + 2 * 32 * 132);
    float (*Sc)[129] = (float(*)[129])(sm + 2 * 32 * 132 + 128 * 32);
    const int bh = blockIdx.x;
    const int b = bh >> 3, h = bh & 7;
    const int tid = threadIdx.x;

    {
        const int r = tid >> 1;
        const int half = tid & 1;
        const float* base = qkv + (size_t)(b * Sdim + r) * QKVS + h * HDim + half * 16;
        const float* qp = base;
        const float* kp = base + 256;
        const float* vp = base + 512;
#pragma unroll
        for (int c = 0; c < 4; c++) {
            int d = half * 16 + c * 4;
            float4 vq = *(const float4*)(qp + c * 4);
            float4 vk = *(const float4*)(kp + c * 4);
            Qs[d+0][r] = vq.x; Qs[d+1][r] = vq.y; Qs[d+2][r] = vq.z; Qs[d+3][r] = vq.w;
            Ks[d+0][r] = vk.x; Ks[d+1][r] = vk.y; Ks[d+2][r] = vk.z; Ks[d+3][r] = vk.w;
            *(float4*)&Vs[r][d] = *(const float4*)(vp + c * 4);
        }
        const int warp = tid >> 5, lane = tid & 31;
        for (int jj = warp; jj < Sdim; jj += 8) {
            float4 t = *(const float4*)(eb + ((size_t)bh * Sdim + jj) * Sdim + lane * 4);
            Sc[lane*4+0][jj] = t.x; Sc[lane*4+1][jj] = t.y;
            Sc[lane*4+2][jj] = t.z; Sc[lane*4+3][jj] = t.w;
        }
    }
    __syncthreads();

    const int ty = tid >> 4, tx = tid & 15;
    const int i0 = ty * 8, j0 = tx * 8;
    float acc[8][8];
#pragma unroll
    for (int i = 0; i < 8; i++)
#pragma unroll
        for (int j = 0; j < 8; j++) acc[i][j] = 0.f;
#pragma unroll
    for (int d = 0; d < 32; d++) {
        float af[8], bf[8];
        *(float4*)&af[0] = *(const float4*)&Qs[d][i0];
        *(float4*)&af[4] = *(const float4*)&Qs[d][i0 + 4];
        *(float4*)&bf[0] = *(const float4*)&Ks[d][j0];
        *(float4*)&bf[4] = *(const float4*)&Ks[d][j0 + 4];
#pragma unroll
        for (int i = 0; i < 8; i++)
#pragma unroll
            for (int j = 0; j < 8; j++) acc[i][j] += af[i] * bf[j];
    }
    const float scale = 0.17677669529663687f;
    const float NEGINF = -__int_as_float(0x7f800000);
#pragma unroll
    for (int ii = 0; ii < 8; ii++) {
        unsigned long long mv =
            *(const unsigned long long*)(mask + ((size_t)bh * Sdim + i0 + ii) * Sdim + j0);
#pragma unroll
        for (int jj = 0; jj < 8; jj++) {
            float s = (acc[ii][jj] + Sc[i0 + ii][j0 + jj]) * scale;
            if ((mv >> (8 * jj)) & 0xffULL) s = NEGINF;
            Sc[i0 + ii][j0 + jj] = s;
        }
    }
    __syncthreads();

    {
        const int warp = tid >> 5, lane = tid & 31;
        for (int r = warp; r < Sdim; r += 8) {
            float vals[4];
#pragma unroll
            for (int c = 0; c < 4; c++) vals[c] = Sc[r][lane + 32 * c];
            float m = fmaxf(fmaxf(vals[0], vals[1]), fmaxf(vals[2], vals[3]));
#pragma unroll
            for (int o = 16; o > 0; o >>= 1) m = fmaxf(m, __shfl_xor_sync(0xffffffffu, m, o));
            float ssum = 0.f;
#pragma unroll
            for (int c = 0; c < 4; c++) { vals[c] = __expf(vals[c] - m); ssum += vals[c]; }
#pragma unroll
            for (int o = 16; o > 0; o >>= 1) ssum += __shfl_xor_sync(0xffffffffu, ssum, o);
            float inv = 1.f / ssum;
            float* ap = attn_out + ((size_t)bh * Sdim + r) * Sdim;
#pragma unroll
            for (int c = 0; c < 4; c++) {
                float p = vals[c] * inv;
                Sc[r][lane + 32 * c] = p;
                ap[lane + 32 * c] = p;
            }
        }
    }
    __syncthreads();

    const int ig = tid >> 3;
    const int dg = tid & 7;
    float o[4][4];
#pragma unroll
    for (int c = 0; c < 4; c++)
#pragma unroll
        for (int e = 0; e < 4; e++) o[c][e] = 0.f;
    for (int j = 0; j < Sdim; j++) {
        float4 vv = *(const float4*)&Vs[j][dg * 4];
#pragma unroll
        for (int c = 0; c < 4; c++) {
            float p = Sc[ig * 4 + c][j];
            o[c][0] += p * vv.x; o[c][1] += p * vv.y;
            o[c][2] += p * vv.z; o[c][3] += p * vv.w;
        }
    }
#pragma unroll
    for (int c = 0; c < 4; c++) {
        float* cp = ctx + (size_t)(b * Sdim + ig * 4 + c) * Ddim + h * HDim + dg * 4;
        *(float4*)cp = make_float4(o[c][0], o[c][1], o[c][2], o[c][3]);
    }
}

// -------- edge-value: ctx[bh,i,d] += sum_j attn[bh,i,j] * ev[i,j,d] --------
#define EV_FLOATS (128*132 + 128*32)
#define EV_BYTES  (EV_FLOATS * 4)
__global__ __launch_bounds__(256) void ev_kernel(
    const float* __restrict__ attn, const float* __restrict__ ev,
    float* __restrict__ ctx)
{
    const int i   = blockIdx.x;
    const int bh0 = blockIdx.y * 128;
    extern __shared__ float sm2[];
    float (*As)[132]  = (float(*)[132])sm2;
    float (*Evs)[32]  = (float(*)[32])(sm2 + 128 * 132);
    const int tid = threadIdx.x;
    {
        const int warp = tid >> 5, lane = tid & 31;
        for (int r = warp; r < 128; r += 8) {
            const float* p = attn + ((size_t)(bh0 + r) * Sdim + i) * Sdim + lane * 4;
            *(float4*)&As[r][lane * 4] = *(const float4*)p;
        }
        const int r2 = tid >> 1, half = tid & 1;
        const float* ep = ev + (size_t)(i * Sdim + r2) * HDim + half * 16;
#pragma unroll
        for (int c = 0; c < 4; c++)
            *(float4*)&Evs[r2][half * 16 + c * 4] = *(const float4*)(ep + c * 4);
    }
    __syncthreads();
    const int tg = tid >> 3;
    const int dg = tid & 7;
    float o[4][4];
#pragma unroll
    for (int c = 0; c < 4; c++)
#pragma unroll
        for (int e = 0; e < 4; e++) o[c][e] = 0.f;
    for (int j = 0; j < Sdim; j++) {
        float4 bv = *(const float4*)&Evs[j][dg * 4];
#pragma unroll
        for (int c = 0; c < 4; c++) {
            float a = As[tg * 4 + c][j];
            o[c][0] += a * bv.x; o[c][1] += a * bv.y;
            o[c][2] += a * bv.z; o[c][3] += a * bv.w;
        }
    }
#pragma unroll
    for (int c = 0; c < 4; c++) {
        const int bh = bh0 + tg * 4 + c;
        const int b = bh >> 3, h = bh & 7;
        float* cp = ctx + (size_t)(b * Sdim + i) * Ddim + h * HDim + dg * 4;
        float4 cur = *(const float4*)cp;
        cur.x += o[c][0]; cur.y += o[c][1]; cur.z += o[c][2]; cur.w += o[c][3];
        *(float4*)cp = cur;
    }
}

// ---------------- layer norm ----------------------------------------------
__global__ __launch_bounds__(256) void ln_kernel(
    const float* __restrict__ in1, const float* __restrict__ in2, float alpha,
    const float* __restrict__ g, const float* __restrict__ b,
    float* __restrict__ out)
{
    const int warp = threadIdx.x >> 5, lane = threadIdx.x & 31;
    const int row = blockIdx.x * 8 + warp;
    const float* p1 = in1 + (size_t)row * Ddim;
    float v[8];
#pragma unroll
    for (int c = 0; c < 8; c++) {
        int col = lane + 32 * c;
        float t = alpha * p1[col];
        if (in2) t += in2[(size_t)row * Ddim + col];
        v[c] = t;
    }
    float s = 0.f;
#pragma unroll
    for (int c = 0; c < 8; c++) s += v[c];
#pragma unroll
    for (int o = 16; o > 0; o >>= 1) s += __shfl_xor_sync(0xffffffffu, s, o);
    float mu = s * (1.f / Ddim);
    float var = 0.f;
#pragma unroll
    for (int c = 0; c < 8; c++) { float d = v[c] - mu; var += d * d; }
#pragma unroll
    for (int o = 16; o > 0; o >>= 1) var += __shfl_xor_sync(0xffffffffu, var, o);
    var *= (1.f / Ddim);
    float inv = rsqrtf(var + 1e-5f);
#pragma unroll
    for (int c = 0; c < 8; c++) {
        int col = lane + 32 * c;
        out[(size_t)row * Ddim + col] = (v[c] - mu) * inv * g[col] + b[col];
    }
}

__global__ void out_transpose(const float* __restrict__ x, float* __restrict__ out)
{
    size_t idx = (size_t)blockIdx.x * 256 + threadIdx.x;
    int d = (int)(idx % Ddim);
    size_t sb = idx / Ddim;
    int bcol = (int)(sb % Bdim);
    int s = (int)(sb / Bdim);
    out[idx] = x[((size_t)bcol * Sdim + s) * Ddim + d];
}

// ---------------- host -----------------------------------------------------
extern "C" void kernel_launch(void* const* d_in, const int* in_sizes, int n_in,
                              void* d_out, int out_size)
{
    const float* facts = (const float*)d_in[0];
    const float* ekey  = (const float*)d_in[1];
    const float* evalp = (const float*)d_in[2];
    const unsigned char* mask = (const unsigned char*)d_in[3];
    const float *Wq, *Wk, *Wv, *Wo, *bq, *bk, *bv, *bo;
    if (in_sizes[5] == Ldim * Ddim) {
        Wq = (const float*)d_in[4];  bq = (const float*)d_in[5];
        Wk = (const float*)d_in[6];  bk = (const float*)d_in[7];
        Wv = (const float*)d_in[8];  bv = (const float*)d_in[9];
        Wo = (const float*)d_in[10]; bo = (const float*)d_in[11];
    } else {
        Wq = (const float*)d_in[4];  Wk = (const float*)d_in[5];
        Wv = (const float*)d_in[6];  Wo = (const float*)d_in[7];
        bq = (const float*)d_in[8];  bk = (const float*)d_in[9];
        bv = (const float*)d_in[10]; bo = (const float*)d_in[11];
    }
    const float* ln1g = (const float*)d_in[12];
    const float* ln1b = (const float*)d_in[13];
    const float* W1   = (const float*)d_in[14];
    const float* b1   = (const float*)d_in[15];
    const float* W2   = (const float*)d_in[16];
    const float* b2   = (const float*)d_in[17];
    const float* ln2g = (const float*)d_in[18];
    const float* ln2b = (const float*)d_in[19];

    float *x, *qkv, *ctx, *tmp, *eb, *at, *ff, *bqkvp;
    __half *wqkvT, *woT, *w1T, *w2T;
    cudaGetSymbolAddress((void**)&x,    g_x);
    cudaGetSymbolAddress((void**)&qkv,  g_qkv);
    cudaGetSymbolAddress((void**)&ctx,  g_ctx);
    cudaGetSymbolAddress((void**)&tmp,  g_tmp);
    cudaGetSymbolAddress((void**)&eb,   g_eb);
    cudaGetSymbolAddress((void**)&at,   g_at);
    cudaGetSymbolAddress((void**)&ff,   g_ff);
    cudaGetSymbolAddress((void**)&wqkvT, g_wqkvT);
    cudaGetSymbolAddress((void**)&woT,  g_woT);
    cudaGetSymbolAddress((void**)&w1T,  g_w1T);
    cudaGetSymbolAddress((void**)&w2T,  g_w2T);
    cudaGetSymbolAddress((void**)&bqkvp, g_bqkv);

    cudaFuncSetAttribute(mma_gemm<false>, cudaFuncAttributeMaxDynamicSharedMemorySize, GSM_BYTES);
    cudaFuncSetAttribute(mma_gemm<true>,  cudaFuncAttributeMaxDynamicSharedMemorySize, GSM_BYTES);
    cudaFuncSetAttribute(attn_kernel, cudaFuncAttributeMaxDynamicSharedMemorySize, ATT_BYTES);
    cudaFuncSetAttribute(ev_kernel,   cudaFuncAttributeMaxDynamicSharedMemorySize, EV_BYTES);

    // launches 0-4 (so ncu -s 5 -c 1 captures the first mma_gemm)
    tr_qkv<<<dim3(8, 8, 3 * Ldim), 256>>>(Wq, Wk, Wv, wqkvT);                       // 0
    tr_h<<<dim3(8, 8, Ldim), 256>>>(Wo, woT, Ddim, Ddim,
        (size_t)Ddim*Ddim, (size_t)Ddim*Ddim);                                      // 1
    tr_h<<<dim3(64, 8, Ldim), 256>>>(W1, w1T, Ddim, Fdim,
        (size_t)Ddim*Fdim, (size_t)Fdim*Ddim);                                      // 2
    tr_h<<<dim3(8, 64, Ldim), 256>>>(W2, w2T, Fdim, Ddim,
        (size_t)Fdim*Ddim, (size_t)Ddim*Fdim);                                      // 3
    prep_kernel<<<NR * Ddim / 256, 256>>>(facts, x, bq, bk, bv, bqkvp);             // 4

    for (int l = 0; l < Ldim; l++) {
        // fused qkv: C[16384,768] = x @ [Wq|Wk|Wv]
        mma_gemm<false><<<dim3(QKVS / 128, NR / 128), 256, GSM_BYTES>>>(
            x, wqkvT + (size_t)l * 3 * Ddim * Ddim, bqkvp + l * QKVS, qkv,
            NR, QKVS, Ddim);                                                        // 5 (l=0)

        ebias_kernel<<<dim3(Sdim, BHdim / 128), 256>>>(qkv, ekey, eb);
        attn_kernel<<<BHdim, 256, ATT_BYTES>>>(qkv, eb, mask, at, ctx);
        ev_kernel<<<dim3(Sdim, BHdim / 128), 256, EV_BYTES>>>(at, evalp, ctx);

        mma_gemm<false><<<dim3(Ddim / 128, NR / 128), 256, GSM_BYTES>>>(
            ctx, woT + (size_t)l * Ddim * Ddim, bo + l * Ddim, tmp,
            NR, Ddim, Ddim);
        ln_kernel<<<NR / 8, 256>>>(tmp, x, 1.f, ln1g + l * Ddim, ln1b + l * Ddim, x);

        mma_gemm<true><<<dim3(Fdim / 128, NR / 128), 256, GSM_BYTES>>>(
            x, w1T + (size_t)l * Fdim * Ddim, b1 + l * Fdim, ff,
            NR, Fdim, Ddim);
        mma_gemm<false><<<dim3(Ddim / 128, NR / 128), 256, GSM_BYTES>>>(
            ff, w2T + (size_t)l * Ddim * Fdim, b2 + l * Ddim, tmp,
            NR, Ddim, Fdim);
        ln_kernel<<<NR / 8, 256>>>(tmp, nullptr, 2.f, ln2g + l * Ddim, ln2b + l * Ddim, x);
    }

    out_transpose<<<NR * Ddim / 256, 256>>>(x, (float*)d_out);
}

// round 6
// speedup vs baseline: 1.1719x; 1.1719x over previous
#include <cuda_runtime.h>
#include <cuda_fp16.h>
#include <cstdint>
#include <math.h>

#define Bdim 128
#define Sdim 128
#define Ddim 256
#define Hdim 8
#define HDim 32
#define Fdim 2048
#define Ldim 4
#define BHdim (Bdim*Hdim)     /* 1024 */
#define NR (Bdim*Sdim)        /* 16384 rows */
#define QKVS 768              /* fused qkv row stride */

// ---------------- scratch (device globals; no allocation allowed) ----------
__device__ float g_x[NR*Ddim];
__device__ float g_qkv[(size_t)NR*QKVS];
__device__ float g_ctx[NR*Ddim];
__device__ float g_tmp[NR*Ddim];
__device__ float g_eb[(size_t)BHdim*Sdim*Sdim];   // [bh][j][i]
__device__ float g_at[(size_t)BHdim*Sdim*Sdim];   // [bh][i][j]
__device__ float g_ff[(size_t)NR*Fdim];
// transposed fp16 weights [N][K]
__device__ __half g_wqkvT[(size_t)Ldim*3*Ddim*Ddim];  // per layer: [768][256]
__device__ __half g_woT[(size_t)Ldim*Ddim*Ddim];      // [256][256]
__device__ __half g_w1T[(size_t)Ldim*Fdim*Ddim];      // [2048][256]
__device__ __half g_w2T[(size_t)Ldim*Ddim*Fdim];      // [256][2048]
__device__ float g_bqkv[Ldim*QKVS];

// ==================== fp16 split-A mma GEMM (ldmatrix) =====================
// C[M,N] = A[M,K] @ BT[N,K]^T + bias, optional relu.
// A fp32 -> (hi,lo) fp16 split; BT fp16. CTA 128x128, 8 warps 32mx64n, CH=32.
#define CH 32
#define SKH 40                          /* smem halves per row (32 + 8 pad) */
#define TILEH (128 * SKH)               /* 5120 halves = 10240 B */
#define GSM_HALVES (6 * TILEH)
#define GSM_BYTES  (GSM_HALVES * 2 + 1024)   /* 61440 + 1K slack */

__device__ __forceinline__ uint32_t smem_u32(const void* p) {
    uint32_t a;
    asm("{ .reg .u64 t; cvta.to.shared.u64 t, %1; cvt.u32.u64 %0, t; }"
        : "=r"(a) : "l"(p));
    return a;
}

#define LDSM_X4(R0,R1,R2,R3,ADDR) \
    asm volatile("ldmatrix.sync.aligned.m8n8.x4.shared.b16 {%0,%1,%2,%3}, [%4];" \
        : "=r"(R0), "=r"(R1), "=r"(R2), "=r"(R3) : "r"(ADDR) : "memory")

__device__ __forceinline__ void mma_f16(
    float& c0, float& c1, float& c2, float& c3,
    uint32_t a0, uint32_t a1, uint32_t a2, uint32_t a3,
    uint32_t b0, uint32_t b1)
{
    asm volatile(
        "mma.sync.aligned.m16n8k16.row.col.f32.f16.f16.f32 "
        "{%0,%1,%2,%3}, {%4,%5,%6,%7}, {%8,%9}, {%0,%1,%2,%3};"
        : "+f"(c0), "+f"(c1), "+f"(c2), "+f"(c3)
        : "r"(a0), "r"(a1), "r"(a2), "r"(a3), "r"(b0), "r"(b1));
}

template<bool RELU>
__global__ __launch_bounds__(256) void mma_gemm(
    const float* __restrict__ A, const __half* __restrict__ BT,
    const float* __restrict__ bias, float* __restrict__ C,
    int M, int N, int K)
{
    extern __shared__ __half sh[];
    // tiles in order: AH0 AL0 B0 AH1 AL1 B1
    const uint32_t s0 = smem_u32(sh);
    const uint32_t AHo[2] = { s0,                 s0 + 3 * TILEH * 2 };
    const uint32_t ALo[2] = { s0 + TILEH * 2,     s0 + 4 * TILEH * 2 };
    const uint32_t BHo[2] = { s0 + 2 * TILEH * 2, s0 + 5 * TILEH * 2 };
    __half* AHp[2] = { sh,             sh + 3 * TILEH };
    __half* ALp[2] = { sh + TILEH,     sh + 4 * TILEH };
    __half* BHp[2] = { sh + 2 * TILEH, sh + 5 * TILEH };

    const int tid = threadIdx.x;
    const int lane = tid & 31, wid = tid >> 5;
    const int wm = (wid >> 1) * 32, wn = (wid & 1) * 64;
    const int m0 = blockIdx.y * 128, n0 = blockIdx.x * 128;
    const float* Abase = A + (size_t)m0 * K;
    const __half* Bbase = BT + (size_t)n0 * K;
    const int nch = K / CH;

    const int srow = tid >> 1;          // 0..127
    const int shalf = tid & 1;          // 16-half half of the chunk

    // ldmatrix lane-local byte offsets (rows stride 80B -> conflict-free)
    const uint32_t a_loff = (uint32_t)(((lane & 15) * SKH + ((lane >> 4) << 3)) * 2);
    const uint32_t b_loff = (uint32_t)((((lane & 7) + ((lane >> 4) << 3)) * SKH
                                        + (((lane >> 3) & 1) << 3)) * 2);

    float4 ra[4];
    uint4 rb[2];
    auto ldg = [&](int c) {
        const float* Ap = Abase + (size_t)srow * K + c * CH + shalf * 16;
#pragma unroll
        for (int i = 0; i < 4; ++i)
            ra[i] = *(const float4*)(Ap + i * 4);
        const __half* Bp = Bbase + (size_t)srow * K + c * CH + shalf * 16;
        rb[0] = *(const uint4*)(Bp);
        rb[1] = *(const uint4*)(Bp + 8);
    };
    auto sts = [&](int buf) {           // buf MUST be 0 or 1
        const int hb = srow * SKH + shalf * 16;
#pragma unroll
        for (int i = 0; i < 4; ++i) {
            float4 v = ra[i];
            __half hx = __float2half_rn(v.x), hy = __float2half_rn(v.y);
            __half hz = __float2half_rn(v.z), hw = __float2half_rn(v.w);
            __half lx = __float2half_rn(v.x - __half2float(hx));
            __half ly = __float2half_rn(v.y - __half2float(hy));
            __half lz = __float2half_rn(v.z - __half2float(hz));
            __half lw = __float2half_rn(v.w - __half2float(hw));
            union { __half h[4]; uint2 u; } ph, pl;
            ph.h[0] = hx; ph.h[1] = hy; ph.h[2] = hz; ph.h[3] = hw;
            pl.h[0] = lx; pl.h[1] = ly; pl.h[2] = lz; pl.h[3] = lw;
            *(uint2*)&AHp[buf][hb + i * 4] = ph.u;
            *(uint2*)&ALp[buf][hb + i * 4] = pl.u;
        }
        *(uint4*)&BHp[buf][hb]     = rb[0];
        *(uint4*)&BHp[buf][hb + 8] = rb[1];
    };

    float acc[2][8][4];
#pragma unroll
    for (int mt = 0; mt < 2; ++mt)
#pragma unroll
        for (int nt = 0; nt < 8; ++nt)
#pragma unroll
            for (int e = 0; e < 4; ++e) acc[mt][nt][e] = 0.f;

    ldg(0);
    sts(0);
    __syncthreads();

    for (int c = 0; c < nch; ++c) {
        if (c + 1 < nch) ldg(c + 1);
        const int buf = c & 1;
        const uint32_t ahb = AHo[buf] + (uint32_t)(wm * SKH * 2) + a_loff;
        const uint32_t alb = ALo[buf] + (uint32_t)(wm * SKH * 2) + a_loff;
        const uint32_t bhb = BHo[buf] + (uint32_t)(wn * SKH * 2) + b_loff;
#pragma unroll
        for (int s = 0; s < 2; ++s) {
            const uint32_t kb2 = s * 32;   // 16 halves = 32 bytes
            uint32_t bfr[8][2];
#pragma unroll
            for (int p = 0; p < 4; ++p) {
                uint32_t r0, r1, r2, r3;
                LDSM_X4(r0, r1, r2, r3,
                        bhb + (uint32_t)(p * 16 * SKH * 2) + kb2);
                bfr[p*2][0] = r0; bfr[p*2][1] = r1;
                bfr[p*2+1][0] = r2; bfr[p*2+1][1] = r3;
            }
            uint32_t ah[2][4], al[2][4];
#pragma unroll
            for (int mt = 0; mt < 2; ++mt) {
                LDSM_X4(ah[mt][0], ah[mt][1], ah[mt][2], ah[mt][3],
                        ahb + (uint32_t)(mt * 16 * SKH * 2) + kb2);
                LDSM_X4(al[mt][0], al[mt][1], al[mt][2], al[mt][3],
                        alb + (uint32_t)(mt * 16 * SKH * 2) + kb2);
            }
            // hi pass: 16 independent accumulators, no RAW pairs
#pragma unroll
            for (int nt = 0; nt < 8; ++nt)
#pragma unroll
                for (int mt = 0; mt < 2; ++mt)
                    mma_f16(acc[mt][nt][0], acc[mt][nt][1],
                            acc[mt][nt][2], acc[mt][nt][3],
                            ah[mt][0], ah[mt][1], ah[mt][2], ah[mt][3],
                            bfr[nt][0], bfr[nt][1]);
            // lo pass
#pragma unroll
            for (int nt = 0; nt < 8; ++nt)
#pragma unroll
                for (int mt = 0; mt < 2; ++mt)
                    mma_f16(acc[mt][nt][0], acc[mt][nt][1],
                            acc[mt][nt][2], acc[mt][nt][3],
                            al[mt][0], al[mt][1], al[mt][2], al[mt][3],
                            bfr[nt][0], bfr[nt][1]);
        }
        if (c + 1 < nch) sts((c + 1) & 1);   // FIX: buffer index, not chunk index
        __syncthreads();
    }

    const int qr = lane >> 2, qc = lane & 3;
#pragma unroll
    for (int mt = 0; mt < 2; ++mt) {
        const int r = m0 + wm + mt * 16 + qr;
#pragma unroll
        for (int nt = 0; nt < 8; ++nt) {
            const int col = n0 + wn + nt * 8 + qc * 2;
            float b0 = bias[col], b1 = bias[col + 1];
            float2 v0, v1;
            v0.x = acc[mt][nt][0] + b0; v0.y = acc[mt][nt][1] + b1;
            v1.x = acc[mt][nt][2] + b0; v1.y = acc[mt][nt][3] + b1;
            if (RELU) {
                v0.x = fmaxf(v0.x, 0.f); v0.y = fmaxf(v0.y, 0.f);
                v1.x = fmaxf(v1.x, 0.f); v1.y = fmaxf(v1.y, 0.f);
            }
            *(float2*)(C + (size_t)r * N + col)       = v0;
            *(float2*)(C + (size_t)(r + 8) * N + col) = v1;
        }
    }
}

// ============ fused weight transpose -> fp16 [N][K] (single launch) ========
__global__ __launch_bounds__(256) void tr_all(
    const float* __restrict__ Wq, const float* __restrict__ Wk,
    const float* __restrict__ Wv, const float* __restrict__ Wo,
    const float* __restrict__ W1, const float* __restrict__ W2,
    __half* __restrict__ wqkvT, __half* __restrict__ woT,
    __half* __restrict__ w1T, __half* __restrict__ w2T)
{
    __shared__ float t[32][33];
    const int tb = blockIdx.x;
    const float* src; __half* dst; int K, N, kx, nx;
    if (tb < 768) {
        int w = tb / 256, r = tb % 256, l = r / 64, q = r % 64;
        src = (w == 0 ? Wq : (w == 1 ? Wk : Wv)) + (size_t)l * 65536;
        dst = wqkvT + (size_t)l * 196608 + (size_t)w * 65536;
        K = 256; N = 256; kx = (q / 8) * 32; nx = (q % 8) * 32;
    } else if (tb < 1024) {
        int r = tb - 768, l = r / 64, q = r % 64;
        src = Wo + (size_t)l * 65536; dst = woT + (size_t)l * 65536;
        K = 256; N = 256; kx = (q / 8) * 32; nx = (q % 8) * 32;
    } else if (tb < 3072) {
        int r = tb - 1024, l = r / 512, q = r % 512;
        src = W1 + (size_t)l * 524288; dst = w1T + (size_t)l * 524288;
        K = 256; N = 2048; kx = (q / 64) * 32; nx = (q % 64) * 32;
    } else {
        int r = tb - 3072, l = r / 512, q = r % 512;
        src = W2 + (size_t)l * 524288; dst = w2T + (size_t)l * 524288;
        K = 2048; N = 256; kx = (q / 8) * 32; nx = (q % 8) * 32;
    }
    const int x = threadIdx.x & 31, y = threadIdx.x >> 5;
#pragma unroll
    for (int yy = y; yy < 32; yy += 8)
        t[yy][x] = src[(size_t)(kx + yy) * N + nx + x];
    __syncthreads();
#pragma unroll
    for (int yy = y; yy < 32; yy += 8)
        dst[(size_t)(nx + yy) * K + kx + x] = __float2half_rn(t[x][yy]);
}

// ---- prep: copy facts -> x, pack qkv bias ----------------------------------
__global__ void prep_kernel(const float* __restrict__ facts, float* __restrict__ x,
                            const float* __restrict__ bq, const float* __restrict__ bk,
                            const float* __restrict__ bv, float* __restrict__ bqkv)
{
    size_t idx = (size_t)blockIdx.x * 256 + threadIdx.x;
    x[idx] = facts[idx];
    if (idx < Ldim * QKVS) {
        int l = (int)(idx / QKVS), j = (int)(idx % QKVS);
        float v;
        if (j < 256)      v = bq[l * 256 + j];
        else if (j < 512) v = bk[l * 256 + j - 256];
        else              v = bv[l * 256 + j - 512];
        bqkv[idx] = v;
    }
}

// -------- edge-key bias: eb[bh][j][i] = sum_d ek[j,i,d] * q[bh,j,d] --------
__global__ __launch_bounds__(256) void ebias_kernel(
    const float* __restrict__ qkv, const float* __restrict__ ek,
    float* __restrict__ eb)
{
    const int j   = blockIdx.x;
    const int bh0 = blockIdx.y * 128;
    __shared__ float Qs[32][132];
    __shared__ float Es[32][132];
    const int tid = threadIdx.x;
    {
        const int r = tid >> 1;
        const int half = tid & 1;
        const int bh = bh0 + r;
        const int b = bh >> 3, h = bh & 7;
        const float* qp = qkv + (size_t)(b * Sdim + j) * QKVS + h * HDim + half * 16;
        const float* ep = ek + (size_t)(j * Sdim + r) * HDim + half * 16;
#pragma unroll
        for (int c = 0; c < 4; c++) {
            float4 vq = *(const float4*)(qp + c * 4);
            float4 ve = *(const float4*)(ep + c * 4);
            int d = half * 16 + c * 4;
            Qs[d+0][r] = vq.x; Qs[d+1][r] = vq.y; Qs[d+2][r] = vq.z; Qs[d+3][r] = vq.w;
            Es[d+0][r] = ve.x; Es[d+1][r] = ve.y; Es[d+2][r] = ve.z; Es[d+3][r] = ve.w;
        }
    }
    __syncthreads();
    const int ty = tid >> 4, tx = tid & 15;
    float acc[8][8];
#pragma unroll
    for (int i = 0; i < 8; i++)
#pragma unroll
        for (int c = 0; c < 8; c++) acc[i][c] = 0.f;
#pragma unroll
    for (int d = 0; d < 32; d++) {
        float af[8], bf[8];
        *(float4*)&af[0] = *(const float4*)&Qs[d][ty * 8];
        *(float4*)&af[4] = *(const float4*)&Qs[d][ty * 8 + 4];
        *(float4*)&bf[0] = *(const float4*)&Es[d][tx * 8];
        *(float4*)&bf[4] = *(const float4*)&Es[d][tx * 8 + 4];
#pragma unroll
        for (int i = 0; i < 8; i++)
#pragma unroll
            for (int c = 0; c < 8; c++) acc[i][c] += af[i] * bf[c];
    }
#pragma unroll
    for (int i = 0; i < 8; i++) {
        float* op = eb + ((size_t)(bh0 + ty * 8 + i) * Sdim + j) * Sdim + tx * 8;
        *(float4*)(op)     = *(float4*)&acc[i][0];
        *(float4*)(op + 4) = *(float4*)&acc[i][4];
    }
}

// -------- attention per (b,h) ---------------------------------------------
#define ATT_FLOATS (2*32*132 + 128*32 + 128*129)
#define ATT_BYTES  (ATT_FLOATS * 4)
__global__ __launch_bounds__(256) void attn_kernel(
    const float* __restrict__ qkv, const float* __restrict__ eb,
    const unsigned char* __restrict__ mask,
    float* __restrict__ attn_out, float* __restrict__ ctx)
{
    extern __shared__ float sm[];
    float (*Qs)[132] = (float(*)[132])sm;
    float (*Ks)[132] = (float(*)[132])(sm + 32 * 132);
    float (*Vs)[32]  = (float(*)[32]) (sm + 2 * 32 * 132);
    float (*Sc)[129] = (float(*)[129])(sm + 2 * 32 * 132 + 128 * 32);
    const int bh = blockIdx.x;
    const int b = bh >> 3, h = bh & 7;
    const int tid = threadIdx.x;

    {
        const int r = tid >> 1;
        const int half = tid & 1;
        const float* base = qkv + (size_t)(b * Sdim + r) * QKVS + h * HDim + half * 16;
        const float* qp = base;
        const float* kp = base + 256;
        const float* vp = base + 512;
#pragma unroll
        for (int c = 0; c < 4; c++) {
            int d = half * 16 + c * 4;
            float4 vq = *(const float4*)(qp + c * 4);
            float4 vk = *(const float4*)(kp + c * 4);
            Qs[d+0][r] = vq.x; Qs[d+1][r] = vq.y; Qs[d+2][r] = vq.z; Qs[d+3][r] = vq.w;
            Ks[d+0][r] = vk.x; Ks[d+1][r] = vk.y; Ks[d+2][r] = vk.z; Ks[d+3][r] = vk.w;
            *(float4*)&Vs[r][d] = *(const float4*)(vp + c * 4);
        }
        const int warp = tid >> 5, lane = tid & 31;
        for (int jj = warp; jj < Sdim; jj += 8) {
            float4 t = *(const float4*)(eb + ((size_t)bh * Sdim + jj) * Sdim + lane * 4);
            Sc[lane*4+0][jj] = t.x; Sc[lane*4+1][jj] = t.y;
            Sc[lane*4+2][jj] = t.z; Sc[lane*4+3][jj] = t.w;
        }
    }
    __syncthreads();

    const int ty = tid >> 4, tx = tid & 15;
    const int i0 = ty * 8, j0 = tx * 8;
    float acc[8][8];
#pragma unroll
    for (int i = 0; i < 8; i++)
#pragma unroll
        for (int j = 0; j < 8; j++) acc[i][j] = 0.f;
#pragma unroll
    for (int d = 0; d < 32; d++) {
        float af[8], bf[8];
        *(float4*)&af[0] = *(const float4*)&Qs[d][i0];
        *(float4*)&af[4] = *(const float4*)&Qs[d][i0 + 4];
        *(float4*)&bf[0] = *(const float4*)&Ks[d][j0];
        *(float4*)&bf[4] = *(const float4*)&Ks[d][j0 + 4];
#pragma unroll
        for (int i = 0; i < 8; i++)
#pragma unroll
            for (int j = 0; j < 8; j++) acc[i][j] += af[i] * bf[j];
    }
    const float scale = 0.17677669529663687f;
    const float NEGINF = -__int_as_float(0x7f800000);
#pragma unroll
    for (int ii = 0; ii < 8; ii++) {
        unsigned long long mv =
            *(const unsigned long long*)(mask + ((size_t)bh * Sdim + i0 + ii) * Sdim + j0);
#pragma unroll
        for (int jj = 0; jj < 8; jj++) {
            float s = (acc[ii][jj] + Sc[i0 + ii][j0 + jj]) * scale;
            if ((mv >> (8 * jj)) & 0xffULL) s = NEGINF;
            Sc[i0 + ii][j0 + jj] = s;
        }
    }
    __syncthreads();

    {
        const int warp = tid >> 5, lane = tid & 31;
        for (int r = warp; r < Sdim; r += 8) {
            float vals[4];
#pragma unroll
            for (int c = 0; c < 4; c++) vals[c] = Sc[r][lane + 32 * c];
            float m = fmaxf(fmaxf(vals[0], vals[1]), fmaxf(vals[2], vals[3]));
#pragma unroll
            for (int o = 16; o > 0; o >>= 1) m = fmaxf(m, __shfl_xor_sync(0xffffffffu, m, o));
            float ssum = 0.f;
#pragma unroll
            for (int c = 0; c < 4; c++) { vals[c] = __expf(vals[c] - m); ssum += vals[c]; }
#pragma unroll
            for (int o = 16; o > 0; o >>= 1) ssum += __shfl_xor_sync(0xffffffffu, ssum, o);
            float inv = 1.f / ssum;
            float* ap = attn_out + ((size_t)bh * Sdim + r) * Sdim;
#pragma unroll
            for (int c = 0; c < 4; c++) {
                float p = vals[c] * inv;
                Sc[r][lane + 32 * c] = p;
                ap[lane + 32 * c] = p;
            }
        }
    }
    __syncthreads();

    const int ig = tid >> 3;
    const int dg = tid & 7;
    float o[4][4];
#pragma unroll
    for (int c = 0; c < 4; c++)
#pragma unroll
        for (int e = 0; e < 4; e++) o[c][e] = 0.f;
    for (int j = 0; j < Sdim; j++) {
        float4 vv = *(const float4*)&Vs[j][dg * 4];
#pragma unroll
        for (int c = 0; c < 4; c++) {
            float p = Sc[ig * 4 + c][j];
            o[c][0] += p * vv.x; o[c][1] += p * vv.y;
            o[c][2] += p * vv.z; o[c][3] += p * vv.w;
        }
    }
#pragma unroll
    for (int c = 0; c < 4; c++) {
        float* cp = ctx + (size_t)(b * Sdim + ig * 4 + c) * Ddim + h * HDim + dg * 4;
        *(float4*)cp = make_float4(o[c][0], o[c][1], o[c][2], o[c][3]);
    }
}

// -------- edge-value: ctx[bh,i,d] += sum_j attn[bh,i,j] * ev[i,j,d] --------
#define EV_FLOATS (128*132 + 128*32)
#define EV_BYTES  (EV_FLOATS * 4)
__global__ __launch_bounds__(256) void ev_kernel(
    const float* __restrict__ attn, const float* __restrict__ ev,
    float* __restrict__ ctx)
{
    const int i   = blockIdx.x;
    const int bh0 = blockIdx.y * 128;
    extern __shared__ float sm2[];
    float (*As)[132]  = (float(*)[132])sm2;
    float (*Evs)[32]  = (float(*)[32])(sm2 + 128 * 132);
    const int tid = threadIdx.x;
    {
        const int warp = tid >> 5, lane = tid & 31;
        for (int r = warp; r < 128; r += 8) {
            const float* p = attn + ((size_t)(bh0 + r) * Sdim + i) * Sdim + lane * 4;
            *(float4*)&As[r][lane * 4] = *(const float4*)p;
        }
        const int r2 = tid >> 1, half = tid & 1;
        const float* ep = ev + (size_t)(i * Sdim + r2) * HDim + half * 16;
#pragma unroll
        for (int c = 0; c < 4; c++)
            *(float4*)&Evs[r2][half * 16 + c * 4] = *(const float4*)(ep + c * 4);
    }
    __syncthreads();
    const int tg = tid >> 3;
    const int dg = tid & 7;
    float o[4][4];
#pragma unroll
    for (int c = 0; c < 4; c++)
#pragma unroll
        for (int e = 0; e < 4; e++) o[c][e] = 0.f;
    for (int j = 0; j < Sdim; j++) {
        float4 bv = *(const float4*)&Evs[j][dg * 4];
#pragma unroll
        for (int c = 0; c < 4; c++) {
            float a = As[tg * 4 + c][j];
            o[c][0] += a * bv.x; o[c][1] += a * bv.y;
            o[c][2] += a * bv.z; o[c][3] += a * bv.w;
        }
    }
#pragma unroll
    for (int c = 0; c < 4; c++) {
        const int bh = bh0 + tg * 4 + c;
        const int b = bh >> 3, h = bh & 7;
        float* cp = ctx + (size_t)(b * Sdim + i) * Ddim + h * HDim + dg * 4;
        float4 cur = *(const float4*)cp;
        cur.x += o[c][0]; cur.y += o[c][1]; cur.z += o[c][2]; cur.w += o[c][3];
        *(float4*)cp = cur;
    }
}

// ---------------- layer norm ----------------------------------------------
__global__ __launch_bounds__(256) void ln_kernel(
    const float* __restrict__ in1, const float* __restrict__ in2, float alpha,
    const float* __restrict__ g, const float* __restrict__ b,
    float* __restrict__ out)
{
    const int warp = threadIdx.x >> 5, lane = threadIdx.x & 31;
    const int row = blockIdx.x * 8 + warp;
    const float* p1 = in1 + (size_t)row * Ddim;
    float v[8];
#pragma unroll
    for (int c = 0; c < 8; c++) {
        int col = lane + 32 * c;
        float t = alpha * p1[col];
        if (in2) t += in2[(size_t)row * Ddim + col];
        v[c] = t;
    }
    float s = 0.f;
#pragma unroll
    for (int c = 0; c < 8; c++) s += v[c];
#pragma unroll
    for (int o = 16; o > 0; o >>= 1) s += __shfl_xor_sync(0xffffffffu, s, o);
    float mu = s * (1.f / Ddim);
    float var = 0.f;
#pragma unroll
    for (int c = 0; c < 8; c++) { float d = v[c] - mu; var += d * d; }
#pragma unroll
    for (int o = 16; o > 0; o >>= 1) var += __shfl_xor_sync(0xffffffffu, var, o);
    var *= (1.f / Ddim);
    float inv = rsqrtf(var + 1e-5f);
#pragma unroll
    for (int c = 0; c < 8; c++) {
        int col = lane + 32 * c;
        out[(size_t)row * Ddim + col] = (v[c] - mu) * inv * g[col] + b[col];
    }
}

__global__ void out_transpose(const float* __restrict__ x, float* __restrict__ out)
{
    size_t idx = (size_t)blockIdx.x * 256 + threadIdx.x;
    int d = (int)(idx % Ddim);
    size_t sb = idx / Ddim;
    int bcol = (int)(sb % Bdim);
    int s = (int)(sb / Bdim);
    out[idx] = x[((size_t)bcol * Sdim + s) * Ddim + d];
}

// ---------------- host -----------------------------------------------------
extern "C" void kernel_launch(void* const* d_in, const int* in_sizes, int n_in,
                              void* d_out, int out_size)
{
    const float* facts = (const float*)d_in[0];
    const float* ekey  = (const float*)d_in[1];
    const float* evalp = (const float*)d_in[2];
    const unsigned char* mask = (const unsigned char*)d_in[3];
    const float *Wq, *Wk, *Wv, *Wo, *bq, *bk, *bv, *bo;
    if (in_sizes[5] == Ldim * Ddim) {
        Wq = (const float*)d_in[4];  bq = (const float*)d_in[5];
        Wk = (const float*)d_in[6];  bk = (const float*)d_in[7];
        Wv = (const float*)d_in[8];  bv = (const float*)d_in[9];
        Wo = (const float*)d_in[10]; bo = (const float*)d_in[11];
    } else {
        Wq = (const float*)d_in[4];  Wk = (const float*)d_in[5];
        Wv = (const float*)d_in[6];  Wo = (const float*)d_in[7];
        bq = (const float*)d_in[8];  bk = (const float*)d_in[9];
        bv = (const float*)d_in[10]; bo = (const float*)d_in[11];
    }
    const float* ln1g = (const float*)d_in[12];
    const float* ln1b = (const float*)d_in[13];
    const float* W1   = (const float*)d_in[14];
    const float* b1   = (const float*)d_in[15];
    const float* W2   = (const float*)d_in[16];
    const float* b2   = (const float*)d_in[17];
    const float* ln2g = (const float*)d_in[18];
    const float* ln2b = (const float*)d_in[19];

    float *x, *qkv, *ctx, *tmp, *eb, *at, *ff, *bqkvp;
    __half *wqkvT, *woT, *w1T, *w2T;
    cudaGetSymbolAddress((void**)&x,    g_x);
    cudaGetSymbolAddress((void**)&qkv,  g_qkv);
    cudaGetSymbolAddress((void**)&ctx,  g_ctx);
    cudaGetSymbolAddress((void**)&tmp,  g_tmp);
    cudaGetSymbolAddress((void**)&eb,   g_eb);
    cudaGetSymbolAddress((void**)&at,   g_at);
    cudaGetSymbolAddress((void**)&ff,   g_ff);
    cudaGetSymbolAddress((void**)&wqkvT, g_wqkvT);
    cudaGetSymbolAddress((void**)&woT,  g_woT);
    cudaGetSymbolAddress((void**)&w1T,  g_w1T);
    cudaGetSymbolAddress((void**)&w2T,  g_w2T);
    cudaGetSymbolAddress((void**)&bqkvp, g_bqkv);

    cudaFuncSetAttribute(mma_gemm<false>, cudaFuncAttributeMaxDynamicSharedMemorySize, GSM_BYTES);
    cudaFuncSetAttribute(mma_gemm<true>,  cudaFuncAttributeMaxDynamicSharedMemorySize, GSM_BYTES);
    cudaFuncSetAttribute(attn_kernel, cudaFuncAttributeMaxDynamicSharedMemorySize, ATT_BYTES);
    cudaFuncSetAttribute(ev_kernel,   cudaFuncAttributeMaxDynamicSharedMemorySize, EV_BYTES);

    // launch 0: all weight transposes; launch 1: prep; launch 2: QKV gemm
    tr_all<<<5120, 256>>>(Wq, Wk, Wv, Wo, W1, W2, wqkvT, woT, w1T, w2T);       // 0
    prep_kernel<<<NR * Ddim / 256, 256>>>(facts, x, bq, bk, bv, bqkvp);        // 1

    for (int l = 0; l < Ldim; l++) {
        mma_gemm<false><<<dim3(QKVS / 128, NR / 128), 256, GSM_BYTES>>>(
            x, wqkvT + (size_t)l * 3 * Ddim * Ddim, bqkvp + l * QKVS, qkv,
            NR, QKVS, Ddim);                                                   // 2 (l=0)

        ebias_kernel<<<dim3(Sdim, BHdim / 128), 256>>>(qkv, ekey, eb);
        attn_kernel<<<BHdim, 256, ATT_BYTES>>>(qkv, eb, mask, at, ctx);
        ev_kernel<<<dim3(Sdim, BHdim / 128), 256, EV_BYTES>>>(at, evalp, ctx);

        mma_gemm<false><<<dim3(Ddim / 128, NR / 128), 256, GSM_BYTES>>>(
            ctx, woT + (size_t)l * Ddim * Ddim, bo + l * Ddim, tmp,
            NR, Ddim, Ddim);
        ln_kernel<<<NR / 8, 256>>>(tmp, x, 1.f, ln1g + l * Ddim, ln1b + l * Ddim, x);

        mma_gemm<true><<<dim3(Fdim / 128, NR / 128), 256, GSM_BYTES>>>(
            x, w1T + (size_t)l * Fdim * Ddim, b1 + l * Fdim, ff,
            NR, Fdim, Ddim);
        mma_gemm<false><<<dim3(Ddim / 128, NR / 128), 256, GSM_BYTES>>>(
            ff, w2T + (size_t)l * Ddim * Fdim, b2 + l * Ddim, tmp,
            NR, Ddim, Fdim);
        ln_kernel<<<NR / 8, 256>>>(tmp, nullptr, 2.f, ln2g + l * Ddim, ln2b + l * Ddim, x);
    }

    out_transpose<<<NR * Ddim / 256, 256>>>(x, (float*)d_out);
}

// round 7
// speedup vs baseline: 1.2749x; 1.0879x over previous
#include <cuda_runtime.h>
#include <cuda_fp16.h>
#include <cstdint>
#include <math.h>

#define Bdim 128
#define Sdim 128
#define Ddim 256
#define Hdim 8
#define HDim 32
#define Fdim 2048
#define Ldim 4
#define BHdim (Bdim*Hdim)     /* 1024 */
#define NR (Bdim*Sdim)        /* 16384 rows */
#define QKVS 768              /* fused qkv row stride */

// ---------------- scratch (device globals; no allocation allowed) ----------
__device__ float g_x[NR*Ddim];
__device__ float g_qkv[(size_t)NR*QKVS];
__device__ float g_ctx[NR*Ddim];
__device__ float g_tmp[NR*Ddim];
__device__ float g_eb[(size_t)BHdim*Sdim*Sdim];   // [bh][j][i]
__device__ float g_at[(size_t)BHdim*Sdim*Sdim];   // [bh][i][j]
// fp16 hi/lo activation pairs
__device__ __half g_xh[NR*Ddim];
__device__ __half g_xl[NR*Ddim];
__device__ __half g_ch[NR*Ddim];
__device__ __half g_cl[NR*Ddim];
__device__ __half g_ffh[(size_t)NR*Fdim];
__device__ __half g_ffl[(size_t)NR*Fdim];
// transposed fp16 weights [N][K]
__device__ __half g_wqkvT[(size_t)Ldim*3*Ddim*Ddim];
__device__ __half g_woT[(size_t)Ldim*Ddim*Ddim];
__device__ __half g_w1T[(size_t)Ldim*Fdim*Ddim];
__device__ __half g_w2T[(size_t)Ldim*Ddim*Fdim];
__device__ float g_bqkv[Ldim*QKVS];

// ==================== helpers =============================================
__device__ __forceinline__ uint32_t smem_u32(const void* p) {
    uint32_t a;
    asm("{ .reg .u64 t; cvta.to.shared.u64 t, %1; cvt.u32.u64 %0, t; }"
        : "=r"(a) : "l"(p));
    return a;
}
#define LDSM_X4(R0,R1,R2,R3,ADDR) \
    asm volatile("ldmatrix.sync.aligned.m8n8.x4.shared.b16 {%0,%1,%2,%3}, [%4];" \
        : "=r"(R0), "=r"(R1), "=r"(R2), "=r"(R3) : "r"(ADDR) : "memory")
#define CP16(dst, src) \
    asm volatile("cp.async.cg.shared.global [%0], [%1], 16;" :: "r"(dst), "l"(src))
#define CPCOMMIT() asm volatile("cp.async.commit_group;" ::: "memory")
#define CPWAIT1()  asm volatile("cp.async.wait_group 1;" ::: "memory")
#define CPWAIT0()  asm volatile("cp.async.wait_group 0;" ::: "memory")

__device__ __forceinline__ void mma_f16(
    float& c0, float& c1, float& c2, float& c3,
    uint32_t a0, uint32_t a1, uint32_t a2, uint32_t a3,
    uint32_t b0, uint32_t b1)
{
    asm volatile(
        "mma.sync.aligned.m16n8k16.row.col.f32.f16.f16.f32 "
        "{%0,%1,%2,%3}, {%4,%5,%6,%7}, {%8,%9}, {%0,%1,%2,%3};"
        : "+f"(c0), "+f"(c1), "+f"(c2), "+f"(c3)
        : "r"(a0), "r"(a1), "r"(a2), "r"(a3), "r"(b0), "r"(b1));
}

__device__ __forceinline__ void split16(float v, __half& h, __half& l) {
    h = __float2half_rn(v);
    l = __float2half_rn(v - __half2float(h));
}

// ==================== fp16 split-A mma GEMM (cp.async, 3-stage) ============
// C[M,N] = (Ah+Al)[M,K] @ BT[N,K]^T + bias. Optional relu + fp16 hi/lo out.
#define CH 32
#define SKH 40                          /* smem halves per row (32 + 8 pad) */
#define TILEB (128 * SKH * 2)           /* 10240 B per tile */
#define CHUNKB (3 * TILEB)              /* AH + AL + B per stage */
#define NSTG 3
#define GSMB (NSTG * CHUNKB)            /* 92160 B */

template<bool RELU, bool OUTH>
__global__ __launch_bounds__(256, 2) void mma_gemm(
    const __half* __restrict__ Ah, const __half* __restrict__ Al,
    const __half* __restrict__ BT, const float* __restrict__ bias,
    float* __restrict__ C, __half* __restrict__ Ch, __half* __restrict__ Cl,
    int M, int N, int K)
{
    extern __shared__ __half sh[];
    const uint32_t s0 = smem_u32(sh);
    const int tid = threadIdx.x;
    const int lane = tid & 31, wid = tid >> 5;
    const int wm = (wid >> 1) * 32, wn = (wid & 1) * 64;
    const int m0 = blockIdx.y * 128, n0 = blockIdx.x * 128;
    const int nch = K / CH;
    const int srow = tid >> 1, shalf = tid & 1;

    const __half* Abase = Ah + (size_t)(m0 + srow) * K + shalf * 16;
    const __half* Lbase = Al + (size_t)(m0 + srow) * K + shalf * 16;
    const __half* Bbase = BT + (size_t)(n0 + srow) * K + shalf * 16;
    const uint32_t sdst = (uint32_t)((srow * SKH + shalf * 16) * 2);

    const uint32_t a_loff = (uint32_t)(((lane & 15) * SKH + ((lane >> 4) << 3)) * 2);
    const uint32_t b_loff = (uint32_t)((((lane & 7) + ((lane >> 4) << 3)) * SKH
                                        + (((lane >> 3) & 1) << 3)) * 2);

    auto issue = [&](int c) {
        const uint32_t base = s0 + (uint32_t)((c % NSTG) * CHUNKB) + sdst;
        const __half* ap = Abase + c * CH;
        const __half* lp = Lbase + c * CH;
        const __half* bp = Bbase + c * CH;
        CP16(base,              ap);     CP16(base + 16,              ap + 8);
        CP16(base + TILEB,      lp);     CP16(base + TILEB + 16,      lp + 8);
        CP16(base + 2 * TILEB,  bp);     CP16(base + 2 * TILEB + 16,  bp + 8);
        CPCOMMIT();
    };

    float acc[2][8][4];
#pragma unroll
    for (int mt = 0; mt < 2; ++mt)
#pragma unroll
        for (int nt = 0; nt < 8; ++nt)
#pragma unroll
            for (int e = 0; e < 4; ++e) acc[mt][nt][e] = 0.f;

    issue(0);
    if (nch > 1) issue(1);

    for (int c = 0; c < nch; ++c) {
        if (c + 1 < nch) { CPWAIT1(); } else { CPWAIT0(); }
        __syncthreads();
        if (c + 2 < nch) issue(c + 2);

        const uint32_t stg = s0 + (uint32_t)((c % NSTG) * CHUNKB);
        const uint32_t ahb = stg + (uint32_t)(wm * SKH * 2) + a_loff;
        const uint32_t alb = ahb + TILEB;
        const uint32_t bhb = stg + 2 * TILEB + (uint32_t)(wn * SKH * 2) + b_loff;
#pragma unroll
        for (int s = 0; s < 2; ++s) {
            const uint32_t kb2 = s * 32;   // 16 halves = 32 bytes
            uint32_t bfr[8][2];
#pragma unroll
            for (int p = 0; p < 4; ++p) {
                uint32_t r0, r1, r2, r3;
                LDSM_X4(r0, r1, r2, r3,
                        bhb + (uint32_t)(p * 16 * SKH * 2) + kb2);
                bfr[p*2][0] = r0; bfr[p*2][1] = r1;
                bfr[p*2+1][0] = r2; bfr[p*2+1][1] = r3;
            }
            uint32_t ah[2][4], al[2][4];
#pragma unroll
            for (int mt = 0; mt < 2; ++mt) {
                LDSM_X4(ah[mt][0], ah[mt][1], ah[mt][2], ah[mt][3],
                        ahb + (uint32_t)(mt * 16 * SKH * 2) + kb2);
                LDSM_X4(al[mt][0], al[mt][1], al[mt][2], al[mt][3],
                        alb + (uint32_t)(mt * 16 * SKH * 2) + kb2);
            }
#pragma unroll
            for (int nt = 0; nt < 8; ++nt)
#pragma unroll
                for (int mt = 0; mt < 2; ++mt)
                    mma_f16(acc[mt][nt][0], acc[mt][nt][1],
                            acc[mt][nt][2], acc[mt][nt][3],
                            ah[mt][0], ah[mt][1], ah[mt][2], ah[mt][3],
                            bfr[nt][0], bfr[nt][1]);
#pragma unroll
            for (int nt = 0; nt < 8; ++nt)
#pragma unroll
                for (int mt = 0; mt < 2; ++mt)
                    mma_f16(acc[mt][nt][0], acc[mt][nt][1],
                            acc[mt][nt][2], acc[mt][nt][3],
                            al[mt][0], al[mt][1], al[mt][2], al[mt][3],
                            bfr[nt][0], bfr[nt][1]);
        }
    }

    const int qr = lane >> 2, qc = lane & 3;
#pragma unroll
    for (int mt = 0; mt < 2; ++mt) {
        const int r = m0 + wm + mt * 16 + qr;
#pragma unroll
        for (int nt = 0; nt < 8; ++nt) {
            const int col = n0 + wn + nt * 8 + qc * 2;
            float b0 = bias[col], b1 = bias[col + 1];
            float v00 = acc[mt][nt][0] + b0, v01 = acc[mt][nt][1] + b1;
            float v10 = acc[mt][nt][2] + b0, v11 = acc[mt][nt][3] + b1;
            if (RELU) {
                v00 = fmaxf(v00, 0.f); v01 = fmaxf(v01, 0.f);
                v10 = fmaxf(v10, 0.f); v11 = fmaxf(v11, 0.f);
            }
            if (OUTH) {
                __half h00, l00, h01, l01, h10, l10, h11, l11;
                split16(v00, h00, l00); split16(v01, h01, l01);
                split16(v10, h10, l10); split16(v11, h11, l11);
                *(__half2*)(Ch + (size_t)r * N + col)       = __halves2half2(h00, h01);
                *(__half2*)(Cl + (size_t)r * N + col)       = __halves2half2(l00, l01);
                *(__half2*)(Ch + (size_t)(r + 8) * N + col) = __halves2half2(h10, h11);
                *(__half2*)(Cl + (size_t)(r + 8) * N + col) = __halves2half2(l10, l11);
            } else {
                *(float2*)(C + (size_t)r * N + col)       = make_float2(v00, v01);
                *(float2*)(C + (size_t)(r + 8) * N + col) = make_float2(v10, v11);
            }
        }
    }
}

// ============ fused weight transpose -> fp16 [N][K] (single launch) ========
__global__ __launch_bounds__(256) void tr_all(
    const float* __restrict__ Wq, const float* __restrict__ Wk,
    const float* __restrict__ Wv, const float* __restrict__ Wo,
    const float* __restrict__ W1, const float* __restrict__ W2,
    __half* __restrict__ wqkvT, __half* __restrict__ woT,
    __half* __restrict__ w1T, __half* __restrict__ w2T)
{
    __shared__ float t[32][33];
    const int tb = blockIdx.x;
    const float* src; __half* dst; int K, N, kx, nx;
    if (tb < 768) {
        int w = tb / 256, r = tb % 256, l = r / 64, q = r % 64;
        src = (w == 0 ? Wq : (w == 1 ? Wk : Wv)) + (size_t)l * 65536;
        dst = wqkvT + (size_t)l * 196608 + (size_t)w * 65536;
        K = 256; N = 256; kx = (q / 8) * 32; nx = (q % 8) * 32;
    } else if (tb < 1024) {
        int r = tb - 768, l = r / 64, q = r % 64;
        src = Wo + (size_t)l * 65536; dst = woT + (size_t)l * 65536;
        K = 256; N = 256; kx = (q / 8) * 32; nx = (q % 8) * 32;
    } else if (tb < 3072) {
        int r = tb - 1024, l = r / 512, q = r % 512;
        src = W1 + (size_t)l * 524288; dst = w1T + (size_t)l * 524288;
        K = 256; N = 2048; kx = (q / 64) * 32; nx = (q % 64) * 32;
    } else {
        int r = tb - 3072, l = r / 512, q = r % 512;
        src = W2 + (size_t)l * 524288; dst = w2T + (size_t)l * 524288;
        K = 2048; N = 256; kx = (q / 8) * 32; nx = (q % 8) * 32;
    }
    const int x = threadIdx.x & 31, y = threadIdx.x >> 5;
#pragma unroll
    for (int yy = y; yy < 32; yy += 8)
        t[yy][x] = src[(size_t)(kx + yy) * N + nx + x];
    __syncthreads();
#pragma unroll
    for (int yy = y; yy < 32; yy += 8)
        dst[(size_t)(nx + yy) * K + kx + x] = __float2half_rn(t[x][yy]);
}

// ---- prep: copy facts -> x + hi/lo split ----------------------------------
__global__ void prep_kernel(const float* __restrict__ facts, float* __restrict__ x,
                            __half* __restrict__ xh, __half* __restrict__ xl)
{
    size_t idx = (size_t)blockIdx.x * 256 + threadIdx.x;
    float v = facts[idx];
    x[idx] = v;
    __half h, l;
    split16(v, h, l);
    xh[idx] = h; xl[idx] = l;
}

__global__ void pack_bias(const float* bq, const float* bk, const float* bv,
                          float* out)
{
    int idx = blockIdx.x * 256 + threadIdx.x;
    if (idx >= Ldim * QKVS) return;
    int l = idx / QKVS, j = idx % QKVS;
    float v;
    if (j < 256)      v = bq[l * 256 + j];
    else if (j < 512) v = bk[l * 256 + j - 256];
    else              v = bv[l * 256 + j - 512];
    out[idx] = v;
}

// -------- edge-key bias: eb[bh][j][i] = sum_d ek[j,i,d] * q[bh,j,d] --------
__global__ __launch_bounds__(256) void ebias_kernel(
    const float* __restrict__ qkv, const float* __restrict__ ek,
    float* __restrict__ eb)
{
    const int j   = blockIdx.x;
    const int bh0 = blockIdx.y * 128;
    __shared__ float Qs[32][132];
    __shared__ float Es[32][132];
    const int tid = threadIdx.x;
    {
        const int r = tid >> 1;
        const int half = tid & 1;
        const int bh = bh0 + r;
        const int b = bh >> 3, h = bh & 7;
        const float* qp = qkv + (size_t)(b * Sdim + j) * QKVS + h * HDim + half * 16;
        const float* ep = ek + (size_t)(j * Sdim + r) * HDim + half * 16;
#pragma unroll
        for (int c = 0; c < 4; c++) {
            float4 vq = *(const float4*)(qp + c * 4);
            float4 ve = *(const float4*)(ep + c * 4);
            int d = half * 16 + c * 4;
            Qs[d+0][r] = vq.x; Qs[d+1][r] = vq.y; Qs[d+2][r] = vq.z; Qs[d+3][r] = vq.w;
            Es[d+0][r] = ve.x; Es[d+1][r] = ve.y; Es[d+2][r] = ve.z; Es[d+3][r] = ve.w;
        }
    }
    __syncthreads();
    const int ty = tid >> 4, tx = tid & 15;
    float acc[8][8];
#pragma unroll
    for (int i = 0; i < 8; i++)
#pragma unroll
        for (int c = 0; c < 8; c++) acc[i][c] = 0.f;
#pragma unroll
    for (int d = 0; d < 32; d++) {
        float af[8], bf[8];
        *(float4*)&af[0] = *(const float4*)&Qs[d][ty * 8];
        *(float4*)&af[4] = *(const float4*)&Qs[d][ty * 8 + 4];
        *(float4*)&bf[0] = *(const float4*)&Es[d][tx * 8];
        *(float4*)&bf[4] = *(const float4*)&Es[d][tx * 8 + 4];
#pragma unroll
        for (int i = 0; i < 8; i++)
#pragma unroll
            for (int c = 0; c < 8; c++) acc[i][c] += af[i] * bf[c];
    }
#pragma unroll
    for (int i = 0; i < 8; i++) {
        float* op = eb + ((size_t)(bh0 + ty * 8 + i) * Sdim + j) * Sdim + tx * 8;
        *(float4*)(op)     = *(float4*)&acc[i][0];
        *(float4*)(op + 4) = *(float4*)&acc[i][4];
    }
}

// -------- attention per (b,h) ---------------------------------------------
#define ATT_FLOATS (2*32*132 + 128*32 + 128*129)
#define ATT_BYTES  (ATT_FLOATS * 4)
__global__ __launch_bounds__(256) void attn_kernel(
    const float* __restrict__ qkv, const float* __restrict__ eb,
    const unsigned char* __restrict__ mask,
    float* __restrict__ attn_out, float* __restrict__ ctx)
{
    extern __shared__ float sm[];
    float (*Qs)[132] = (float(*)[132])sm;
    float (*Ks)[132] = (float(*)[132])(sm + 32 * 132);
    float (*Vs)[32]  = (float(*)[32]) (sm + 2 * 32 * 132);
    float (*Sc)[129] = (float(*)[129])(sm + 2 * 32 * 132 + 128 * 32);
    const int bh = blockIdx.x;
    const int b = bh >> 3, h = bh & 7;
    const int tid = threadIdx.x;

    {
        const int r = tid >> 1;
        const int half = tid & 1;
        const float* base = qkv + (size_t)(b * Sdim + r) * QKVS + h * HDim + half * 16;
        const float* qp = base;
        const float* kp = base + 256;
        const float* vp = base + 512;
#pragma unroll
        for (int c = 0; c < 4; c++) {
            int d = half * 16 + c * 4;
            float4 vq = *(const float4*)(qp + c * 4);
            float4 vk = *(const float4*)(kp + c * 4);
            Qs[d+0][r] = vq.x; Qs[d+1][r] = vq.y; Qs[d+2][r] = vq.z; Qs[d+3][r] = vq.w;
            Ks[d+0][r] = vk.x; Ks[d+1][r] = vk.y; Ks[d+2][r] = vk.z; Ks[d+3][r] = vk.w;
            *(float4*)&Vs[r][d] = *(const float4*)(vp + c * 4);
        }
        const int warp = tid >> 5, lane = tid & 31;
        for (int jj = warp; jj < Sdim; jj += 8) {
            float4 t = *(const float4*)(eb + ((size_t)bh * Sdim + jj) * Sdim + lane * 4);
            Sc[lane*4+0][jj] = t.x; Sc[lane*4+1][jj] = t.y;
            Sc[lane*4+2][jj] = t.z; Sc[lane*4+3][jj] = t.w;
        }
    }
    __syncthreads();

    const int ty = tid >> 4, tx = tid & 15;
    const int i0 = ty * 8, j0 = tx * 8;
    float acc[8][8];
#pragma unroll
    for (int i = 0; i < 8; i++)
#pragma unroll
        for (int j = 0; j < 8; j++) acc[i][j] = 0.f;
#pragma unroll
    for (int d = 0; d < 32; d++) {
        float af[8], bf[8];
        *(float4*)&af[0] = *(const float4*)&Qs[d][i0];
        *(float4*)&af[4] = *(const float4*)&Qs[d][i0 + 4];
        *(float4*)&bf[0] = *(const float4*)&Ks[d][j0];
        *(float4*)&bf[4] = *(const float4*)&Ks[d][j0 + 4];
#pragma unroll
        for (int i = 0; i < 8; i++)
#pragma unroll
            for (int j = 0; j < 8; j++) acc[i][j] += af[i] * bf[j];
    }
    const float scale = 0.17677669529663687f;
    const float NEGINF = -__int_as_float(0x7f800000);
#pragma unroll
    for (int ii = 0; ii < 8; ii++) {
        unsigned long long mv =
            *(const unsigned long long*)(mask + ((size_t)bh * Sdim + i0 + ii) * Sdim + j0);
#pragma unroll
        for (int jj = 0; jj < 8; jj++) {
            float s = (acc[ii][jj] + Sc[i0 + ii][j0 + jj]) * scale;
            if ((mv >> (8 * jj)) & 0xffULL) s = NEGINF;
            Sc[i0 + ii][j0 + jj] = s;
        }
    }
    __syncthreads();

    {
        const int warp = tid >> 5, lane = tid & 31;
        for (int r = warp; r < Sdim; r += 8) {
            float vals[4];
#pragma unroll
            for (int c = 0; c < 4; c++) vals[c] = Sc[r][lane + 32 * c];
            float m = fmaxf(fmaxf(vals[0], vals[1]), fmaxf(vals[2], vals[3]));
#pragma unroll
            for (int o = 16; o > 0; o >>= 1) m = fmaxf(m, __shfl_xor_sync(0xffffffffu, m, o));
            float ssum = 0.f;
#pragma unroll
            for (int c = 0; c < 4; c++) { vals[c] = __expf(vals[c] - m); ssum += vals[c]; }
#pragma unroll
            for (int o = 16; o > 0; o >>= 1) ssum += __shfl_xor_sync(0xffffffffu, ssum, o);
            float inv = 1.f / ssum;
            float* ap = attn_out + ((size_t)bh * Sdim + r) * Sdim;
#pragma unroll
            for (int c = 0; c < 4; c++) {
                float p = vals[c] * inv;
                Sc[r][lane + 32 * c] = p;
                ap[lane + 32 * c] = p;
            }
        }
    }
    __syncthreads();

    const int ig = tid >> 3;
    const int dg = tid & 7;
    float o[4][4];
#pragma unroll
    for (int c = 0; c < 4; c++)
#pragma unroll
        for (int e = 0; e < 4; e++) o[c][e] = 0.f;
    for (int j = 0; j < Sdim; j++) {
        float4 vv = *(const float4*)&Vs[j][dg * 4];
#pragma unroll
        for (int c = 0; c < 4; c++) {
            float p = Sc[ig * 4 + c][j];
            o[c][0] += p * vv.x; o[c][1] += p * vv.y;
            o[c][2] += p * vv.z; o[c][3] += p * vv.w;
        }
    }
#pragma unroll
    for (int c = 0; c < 4; c++) {
        float* cp = ctx + (size_t)(b * Sdim + ig * 4 + c) * Ddim + h * HDim + dg * 4;
        *(float4*)cp = make_float4(o[c][0], o[c][1], o[c][2], o[c][3]);
    }
}

// -------- edge-value: ctx += attn @ ev, then hi/lo split out ---------------
#define EV_FLOATS (128*132 + 128*32)
#define EV_BYTES  (EV_FLOATS * 4)
__global__ __launch_bounds__(256) void ev_kernel(
    const float* __restrict__ attn, const float* __restrict__ ev,
    const float* __restrict__ ctx,
    __half* __restrict__ ch, __half* __restrict__ cl)
{
    const int i   = blockIdx.x;
    const int bh0 = blockIdx.y * 128;
    extern __shared__ float sm2[];
    float (*As)[132]  = (float(*)[132])sm2;
    float (*Evs)[32]  = (float(*)[32])(sm2 + 128 * 132);
    const int tid = threadIdx.x;
    {
        const int warp = tid >> 5, lane = tid & 31;
        for (int r = warp; r < 128; r += 8) {
            const float* p = attn + ((size_t)(bh0 + r) * Sdim + i) * Sdim + lane * 4;
            *(float4*)&As[r][lane * 4] = *(const float4*)p;
        }
        const int r2 = tid >> 1, half = tid & 1;
        const float* ep = ev + (size_t)(i * Sdim + r2) * HDim + half * 16;
#pragma unroll
        for (int c = 0; c < 4; c++)
            *(float4*)&Evs[r2][half * 16 + c * 4] = *(const float4*)(ep + c * 4);
    }
    __syncthreads();
    const int tg = tid >> 3;
    const int dg = tid & 7;
    float o[4][4];
#pragma unroll
    for (int c = 0; c < 4; c++)
#pragma unroll
        for (int e = 0; e < 4; e++) o[c][e] = 0.f;
    for (int j = 0; j < Sdim; j++) {
        float4 bv = *(const float4*)&Evs[j][dg * 4];
#pragma unroll
        for (int c = 0; c < 4; c++) {
            float a = As[tg * 4 + c][j];
            o[c][0] += a * bv.x; o[c][1] += a * bv.y;
            o[c][2] += a * bv.z; o[c][3] += a * bv.w;
        }
    }
#pragma unroll
    for (int c = 0; c < 4; c++) {
        const int bh = bh0 + tg * 4 + c;
        const int b = bh >> 3, h = bh & 7;
        const size_t idx = (size_t)(b * Sdim + i) * Ddim + h * HDim + dg * 4;
        float4 cur = *(const float4*)(ctx + idx);
        cur.x += o[c][0]; cur.y += o[c][1]; cur.z += o[c][2]; cur.w += o[c][3];
        __half hh[4], ll[4];
        split16(cur.x, hh[0], ll[0]); split16(cur.y, hh[1], ll[1]);
        split16(cur.z, hh[2], ll[2]); split16(cur.w, hh[3], ll[3]);
        *(__half2*)(ch + idx)     = __halves2half2(hh[0], hh[1]);
        *(__half2*)(ch + idx + 2) = __halves2half2(hh[2], hh[3]);
        *(__half2*)(cl + idx)     = __halves2half2(ll[0], ll[1]);
        *(__half2*)(cl + idx + 2) = __halves2half2(ll[2], ll[3]);
    }
}

// ---------------- layer norm (+ hi/lo split out) ---------------------------
__global__ __launch_bounds__(256) void ln_kernel(
    const float* __restrict__ in1, const float* __restrict__ in2, float alpha,
    const float* __restrict__ g, const float* __restrict__ b,
    float* __restrict__ out, __half* __restrict__ outh, __half* __restrict__ outl)
{
    const int warp = threadIdx.x >> 5, lane = threadIdx.x & 31;
    const int row = blockIdx.x * 8 + warp;
    const float* p1 = in1 + (size_t)row * Ddim;
    float v[8];
#pragma unroll
    for (int c = 0; c < 8; c++) {
        int col = lane + 32 * c;
        float t = alpha * p1[col];
        if (in2) t += in2[(size_t)row * Ddim + col];
        v[c] = t;
    }
    float s = 0.f;
#pragma unroll
    for (int c = 0; c < 8; c++) s += v[c];
#pragma unroll
    for (int o = 16; o > 0; o >>= 1) s += __shfl_xor_sync(0xffffffffu, s, o);
    float mu = s * (1.f / Ddim);
    float var = 0.f;
#pragma unroll
    for (int c = 0; c < 8; c++) { float d = v[c] - mu; var += d * d; }
#pragma unroll
    for (int o = 16; o > 0; o >>= 1) var += __shfl_xor_sync(0xffffffffu, var, o);
    var *= (1.f / Ddim);
    float inv = rsqrtf(var + 1e-5f);
#pragma unroll
    for (int c = 0; c < 8; c++) {
        int col = lane + 32 * c;
        float r = (v[c] - mu) * inv * g[col] + b[col];
        out[(size_t)row * Ddim + col] = r;
        __half h, l;
        split16(r, h, l);
        outh[(size_t)row * Ddim + col] = h;
        outl[(size_t)row * Ddim + col] = l;
    }
}

__global__ void out_transpose(const float* __restrict__ x, float* __restrict__ out)
{
    size_t idx = (size_t)blockIdx.x * 256 + threadIdx.x;
    int d = (int)(idx % Ddim);
    size_t sb = idx / Ddim;
    int bcol = (int)(sb % Bdim);
    int s = (int)(sb / Bdim);
    out[idx] = x[((size_t)bcol * Sdim + s) * Ddim + d];
}

// ---------------- host -----------------------------------------------------
extern "C" void kernel_launch(void* const* d_in, const int* in_sizes, int n_in,
                              void* d_out, int out_size)
{
    const float* facts = (const float*)d_in[0];
    const float* ekey  = (const float*)d_in[1];
    const float* evalp = (const float*)d_in[2];
    const unsigned char* mask = (const unsigned char*)d_in[3];
    const float *Wq, *Wk, *Wv, *Wo, *bq, *bk, *bv, *bo;
    if (in_sizes[5] == Ldim * Ddim) {
        Wq = (const float*)d_in[4];  bq = (const float*)d_in[5];
        Wk = (const float*)d_in[6];  bk = (const float*)d_in[7];
        Wv = (const float*)d_in[8];  bv = (const float*)d_in[9];
        Wo = (const float*)d_in[10]; bo = (const float*)d_in[11];
    } else {
        Wq = (const float*)d_in[4];  Wk = (const float*)d_in[5];
        Wv = (const float*)d_in[6];  Wo = (const float*)d_in[7];
        bq = (const float*)d_in[8];  bk = (const float*)d_in[9];
        bv = (const float*)d_in[10]; bo = (const float*)d_in[11];
    }
    const float* ln1g = (const float*)d_in[12];
    const float* ln1b = (const float*)d_in[13];
    const float* W1   = (const float*)d_in[14];
    const float* b1   = (const float*)d_in[15];
    const float* W2   = (const float*)d_in[16];
    const float* b2   = (const float*)d_in[17];
    const float* ln2g = (const float*)d_in[18];
    const float* ln2b = (const float*)d_in[19];

    float *x, *qkv, *ctx, *tmp, *eb, *at, *bqkvp;
    __half *xh, *xl, *ch, *cl, *ffh, *ffl;
    __half *wqkvT, *woT, *w1T, *w2T;
    cudaGetSymbolAddress((void**)&x,    g_x);
    cudaGetSymbolAddress((void**)&qkv,  g_qkv);
    cudaGetSymbolAddress((void**)&ctx,  g_ctx);
    cudaGetSymbolAddress((void**)&tmp,  g_tmp);
    cudaGetSymbolAddress((void**)&eb,   g_eb);
    cudaGetSymbolAddress((void**)&at,   g_at);
    cudaGetSymbolAddress((void**)&xh,   g_xh);
    cudaGetSymbolAddress((void**)&xl,   g_xl);
    cudaGetSymbolAddress((void**)&ch,   g_ch);
    cudaGetSymbolAddress((void**)&cl,   g_cl);
    cudaGetSymbolAddress((void**)&ffh,  g_ffh);
    cudaGetSymbolAddress((void**)&ffl,  g_ffl);
    cudaGetSymbolAddress((void**)&wqkvT, g_wqkvT);
    cudaGetSymbolAddress((void**)&woT,  g_woT);
    cudaGetSymbolAddress((void**)&w1T,  g_w1T);
    cudaGetSymbolAddress((void**)&w2T,  g_w2T);
    cudaGetSymbolAddress((void**)&bqkvp, g_bqkv);

    cudaFuncSetAttribute(mma_gemm<false,false>, cudaFuncAttributeMaxDynamicSharedMemorySize, GSMB);
    cudaFuncSetAttribute(mma_gemm<true,true>,   cudaFuncAttributeMaxDynamicSharedMemorySize, GSMB);
    cudaFuncSetAttribute(attn_kernel, cudaFuncAttributeMaxDynamicSharedMemorySize, ATT_BYTES);
    cudaFuncSetAttribute(ev_kernel,   cudaFuncAttributeMaxDynamicSharedMemorySize, EV_BYTES);

    // launch order: 0 tr_all, 1 prep, 2 pack_bias, 3 QKV gemm (<- ncu target)
    tr_all<<<5120, 256>>>(Wq, Wk, Wv, Wo, W1, W2, wqkvT, woT, w1T, w2T);        // 0
    prep_kernel<<<NR * Ddim / 256, 256>>>(facts, x, xh, xl);                    // 1
    pack_bias<<<(Ldim * QKVS + 255) / 256, 256>>>(bq, bk, bv, bqkvp);           // 2

    for (int l = 0; l < Ldim; l++) {
        mma_gemm<false,false><<<dim3(QKVS / 128, NR / 128), 256, GSMB>>>(
            xh, xl, wqkvT + (size_t)l * 3 * Ddim * Ddim, bqkvp + l * QKVS,
            qkv, nullptr, nullptr, NR, QKVS, Ddim);                             // 3 (l=0)

        ebias_kernel<<<dim3(Sdim, BHdim / 128), 256>>>(qkv, ekey, eb);
        attn_kernel<<<BHdim, 256, ATT_BYTES>>>(qkv, eb, mask, at, ctx);
        ev_kernel<<<dim3(Sdim, BHdim / 128), 256, EV_BYTES>>>(at, evalp, ctx, ch, cl);

        mma_gemm<false,false><<<dim3(Ddim / 128, NR / 128), 256, GSMB>>>(
            ch, cl, woT + (size_t)l * Ddim * Ddim, bo + l * Ddim,
            tmp, nullptr, nullptr, NR, Ddim, Ddim);
        ln_kernel<<<NR / 8, 256>>>(tmp, x, 1.f, ln1g + l * Ddim, ln1b + l * Ddim,
                                   x, xh, xl);

        mma_gemm<true,true><<<dim3(Fdim / 128, NR / 128), 256, GSMB>>>(
            xh, xl, w1T + (size_t)l * Fdim * Ddim, b1 + l * Fdim,
            nullptr, ffh, ffl, NR, Fdim, Ddim);
        mma_gemm<false,false><<<dim3(Ddim / 128, NR / 128), 256, GSMB>>>(
            ffh, ffl, w2T + (size_t)l * Ddim * Fdim, b2 + l * Ddim,
            tmp, nullptr, nullptr, NR, Ddim, Fdim);
        ln_kernel<<<NR / 8, 256>>>(tmp, nullptr, 2.f, ln2g + l * Ddim, ln2b + l * Ddim,
                                   x, xh, xl);
    }

    out_transpose<<<NR * Ddim / 256, 256>>>(x, (float*)d_out);
}